// round 8
// baseline (speedup 1.0000x reference)
#include <cuda_runtime.h>
#include <cuda_fp16.h>
#include <cstdint>
#include <cstddef>

// y[8192,4096] = x @ sign(W)^T + bias.  fp16 mma.sync GEMM (no tcgen05 on
// plain sm_103 PTX target), cp.async 3-stage pipeline, 128x128x64 tiles.
#define DIM_M 8192
#define DIM_N 4096
#define DIM_K 4096
#define BK 64
#define NCH (DIM_K / BK)            // 64
#define STG_BYTES 32768             // A 16K + B 16K per stage
#define SMEM_TOTAL (3 * STG_BYTES)  // 96 KB

__device__ __half g_xh[(size_t)DIM_M * DIM_K];   // 64 MB
__device__ __half g_wb[(size_t)DIM_N * DIM_K];   // 32 MB

__device__ __forceinline__ uint32_t smem_u32(const void* p) {
    uint32_t a;
    asm("{ .reg .u64 t; cvta.to.shared.u64 t, %1; cvt.u32.u64 %0, t; }" : "=r"(a) : "l"(p));
    return a;
}
__device__ __forceinline__ uint32_t swz(uint32_t off) { return off ^ ((off >> 3) & 0x70); }
__device__ __forceinline__ void cp16(uint32_t dst, const void* src) {
    asm volatile("cp.async.cg.shared.global [%0], [%1], 16;" :: "r"(dst), "l"(src));
}
__device__ __forceinline__ void ldm4(uint32_t* r, uint32_t addr) {
    asm volatile("ldmatrix.sync.aligned.m8n8.x4.shared.b16 {%0,%1,%2,%3}, [%4];"
                 : "=r"(r[0]), "=r"(r[1]), "=r"(r[2]), "=r"(r[3]) : "r"(addr));
}
__device__ __forceinline__ void mma16816(float* d, const uint32_t* a,
                                         uint32_t b0, uint32_t b1) {
    asm volatile(
        "mma.sync.aligned.m16n8k16.row.col.f32.f16.f16.f32 "
        "{%0,%1,%2,%3}, {%4,%5,%6,%7}, {%8,%9}, {%0,%1,%2,%3};"
        : "+f"(d[0]), "+f"(d[1]), "+f"(d[2]), "+f"(d[3])
        : "r"(a[0]), "r"(a[1]), "r"(a[2]), "r"(a[3]), "r"(b0), "r"(b1));
}

// One chunk load: A 128x64 fp16 (rows m0.., k0..) + B 128x64 (rows n0..).
__device__ __forceinline__ void load_chunk(uint32_t stage, int m0, int n0, int k0, int tid) {
    const __half* xa = g_xh + (size_t)m0 * DIM_K + k0;
    const __half* wb = g_wb + (size_t)n0 * DIM_K + k0;
    #pragma unroll
    for (int i = tid; i < 1024; i += 256) {         // 128 rows x 8 x 16B
        int r = i >> 3, c = i & 7;
        uint32_t d = swz((uint32_t)(r * 128 + c * 16));
        cp16(stage + d, xa + (size_t)r * DIM_K + c * 8);
        cp16(stage + 16384 + d, wb + (size_t)r * DIM_K + c * 8);
    }
}

__global__ void __launch_bounds__(256)
binlin_gemm(const float* __restrict__ bias, float* __restrict__ out) {
    extern __shared__ char smem[];
    const int tid = threadIdx.x, lane = tid & 31, w = tid >> 5;
    const int wm = w & 3, wn = w >> 2;              // warp grid 4(m) x 2(n)
    const int m0 = blockIdx.y * 128, n0 = blockIdx.x * 128;
    const uint32_t sb = smem_u32(smem);

    float acc[2][8][4];
    #pragma unroll
    for (int i = 0; i < 2; ++i)
        #pragma unroll
        for (int j = 0; j < 8; ++j)
            #pragma unroll
            for (int t = 0; t < 4; ++t) acc[i][j][t] = 0.f;

    load_chunk(sb, m0, n0, 0, tid);
    asm volatile("cp.async.commit_group;" ::: "memory");
    load_chunk(sb + STG_BYTES, m0, n0, BK, tid);
    asm volatile("cp.async.commit_group;" ::: "memory");

    // ldmatrix per-lane byte offsets (within a stage), swizzled.
    const int lrow = lane & 15, lkh = lane >> 4;    // row 0..15, k-half 0..1
    for (int c = 0; c < NCH; ++c) {
        __syncthreads();                            // prev chunk's reads done
        if (c + 2 < NCH) {
            load_chunk(sb + ((c + 2) % 3) * STG_BYTES, m0, n0, (c + 2) * BK, tid);
            asm volatile("cp.async.commit_group;" ::: "memory");
            asm volatile("cp.async.wait_group 2;" ::: "memory");
        } else if (c + 1 < NCH) {
            asm volatile("cp.async.wait_group 1;" ::: "memory");
        } else {
            asm volatile("cp.async.wait_group 0;" ::: "memory");
        }
        __syncthreads();
        const uint32_t sa = sb + (c % 3) * STG_BYTES;
        const uint32_t sB = sa + 16384;
        #pragma unroll
        for (int ks = 0; ks < 4; ++ks) {
            const uint32_t kb = (uint32_t)(ks * 32 + lkh * 16);
            uint32_t a[8], b[4][4];
            #pragma unroll
            for (int mt = 0; mt < 2; ++mt)
                ldm4(a + mt * 4, sa + swz((uint32_t)((wm * 32 + mt * 16 + lrow) * 128) + kb));
            #pragma unroll
            for (int nt = 0; nt < 4; ++nt)
                ldm4(b[nt], sB + swz((uint32_t)((wn * 64 + nt * 16 + lrow) * 128) + kb));
            #pragma unroll
            for (int mt = 0; mt < 2; ++mt)
                #pragma unroll
                for (int nt = 0; nt < 4; ++nt) {
                    mma16816(acc[mt][nt * 2 + 0], a + mt * 4, b[nt][0], b[nt][2]);
                    mma16816(acc[mt][nt * 2 + 1], a + mt * 4, b[nt][1], b[nt][3]);
                }
        }
    }

    // Epilogue: thread holds (m = base + lane/4 [+8], n = nbase + (lane&3)*2).
    float2 bv[8];
    #pragma unroll
    for (int j = 0; j < 8; ++j)
        bv[j] = *(const float2*)&bias[n0 + wn * 64 + (j >> 1) * 16 + (j & 1) * 8 + (lane & 3) * 2];
    #pragma unroll
    for (int mt = 0; mt < 2; ++mt) {
        const int mrow = m0 + wm * 32 + mt * 16 + (lane >> 2);
        #pragma unroll
        for (int j = 0; j < 8; ++j) {
            const int gn = n0 + wn * 64 + (j >> 1) * 16 + (j & 1) * 8 + (lane & 3) * 2;
            float2 v0 = make_float2(acc[mt][j][0] + bv[j].x, acc[mt][j][1] + bv[j].y);
            float2 v1 = make_float2(acc[mt][j][2] + bv[j].x, acc[mt][j][3] + bv[j].y);
            *(float2*)&out[(size_t)mrow * DIM_N + gn] = v0;
            *(float2*)&out[(size_t)(mrow + 8) * DIM_N + gn] = v1;
        }
    }
}

__global__ void conv_x(const float4* __restrict__ x) {
    const size_t n4 = (size_t)DIM_M * DIM_K / 4;
    uint2* p = (uint2*)g_xh;
    for (size_t i = (size_t)blockIdx.x * blockDim.x + threadIdx.x; i < n4;
         i += (size_t)gridDim.x * blockDim.x) {
        float4 v = x[i];
        __half2 lo = __floats2half2_rn(v.x, v.y);
        __half2 hi = __floats2half2_rn(v.z, v.w);
        uint2 o;
        o.x = *(uint32_t*)&lo;
        o.y = *(uint32_t*)&hi;
        p[i] = o;
    }
}

__global__ void conv_w(const float4* __restrict__ w) {
    const size_t n4 = (size_t)DIM_N * DIM_K / 4;
    ushort4* p = (ushort4*)g_wb;
    for (size_t i = (size_t)blockIdx.x * blockDim.x + threadIdx.x; i < n4;
         i += (size_t)gridDim.x * blockDim.x) {
        float4 v = w[i];
        ushort4 o;
        o.x = (v.x >= 0.f) ? 0x3C00 : 0xBC00;   // +/-1.0 fp16
        o.y = (v.y >= 0.f) ? 0x3C00 : 0xBC00;
        o.z = (v.z >= 0.f) ? 0x3C00 : 0xBC00;
        o.w = (v.w >= 0.f) ? 0x3C00 : 0xBC00;
        p[i] = o;
    }
}

extern "C" void kernel_launch(void* const* d_in, const int* in_sizes, int n_in,
                              void* d_out, int out_size) {
    const float* x = (const float*)d_in[0];
    const float* w = (const float*)d_in[1];
    const float* bias = (const float*)d_in[2];
    float* out = (float*)d_out;
    conv_x<<<2048, 256>>>((const float4*)x);
    conv_w<<<1024, 256>>>((const float4*)w);
    cudaFuncSetAttribute(binlin_gemm, cudaFuncAttributeMaxDynamicSharedMemorySize, SMEM_TOTAL);
    dim3 grid(DIM_N / 128, DIM_M / 128);   // 32 x 64 = 2048 CTAs
    binlin_gemm<<<grid, 256, SMEM_TOTAL>>>(bias, out);
}